// round 6
// baseline (speedup 1.0000x reference)
#include <cuda_runtime.h>
#include <math.h>

#define F        128
#define TWO_F    256
#define KAGG     16
#define TILE     32          // rows per tile
#define NPROD    12          // producer warps
#define THREADS  512
#define B        256

// Scratch (static __device__ arrays: allowed; no runtime allocation)
__device__ float g_h2[65536 * F];   // 33.5 MB
__device__ float g_h1[4096  * F];   // 2 MB
__device__ float g_h0[256   * F];   // 128 KB

// ---- packed f32x2 helpers ------------------------------------------------
__device__ __forceinline__ unsigned long long pack2(float x) {
    unsigned long long r;
    asm("mov.b64 %0, {%1, %1};" : "=l"(r) : "f"(x));
    return r;
}
__device__ __forceinline__ void fma2(unsigned long long& d,
                                     unsigned long long a,
                                     unsigned long long b) {
    asm("fma.rn.f32x2 %0, %1, %2, %0;" : "+l"(d) : "l"(a), "l"(b));
}
__device__ __forceinline__ void unpack2(unsigned long long v, float& lo, float& hi) {
    asm("mov.b64 {%0, %1}, %2;" : "=f"(lo), "=f"(hi) : "l"(v));
}
__device__ __forceinline__ void cpa16(void* dst_smem, const void* src) {
    unsigned d = (unsigned)__cvta_generic_to_shared(dst_smem);
    asm volatile("cp.async.ca.shared.global [%0], [%1], 16;" :: "r"(d), "l"(src));
}

// load 8 consecutive neighbor feature-slices (half a row's K) into regs
#define LOADH(D, P, H)                                            \
    { _Pragma("unroll")                                           \
      for (int k_ = 0; k_ < 8; ++k_)                              \
          D[k_] = (P)[((H) * 8 + k_) * (F / 4)]; }

__device__ __forceinline__ float4 sum8(float4* v) {
    #pragma unroll
    for (int s = 4; s > 0; s >>= 1)
        #pragma unroll
        for (int k = 0; k < s; ++k) {
            v[k].x += v[k + s].x; v[k].y += v[k + s].y;
            v[k].z += v[k + s].z; v[k].w += v[k + s].w;
        }
    return v[0];
}

__device__ __forceinline__ void store_row(float* buf, int r, int lid,
                                          float4 a, float4 b) {
    const float s = 1.0f / 16.0f;
    ((float4*)(buf + r * TWO_F))[lid] =
        make_float4((a.x + b.x) * s, (a.y + b.y) * s,
                    (a.z + b.z) * s, (a.w + b.w) * s);
}

// ---------------------------------------------------------------------------
// Warp-specialized fused SAGE layer.
//   out[r] = relu( concat(mean_k nbr[r*16+k], self[r]) @ W + b )
// Persistent CTAs, 512 threads = 16 warps.
// Warps 0-11 : producers. 3-buffer software-pipelined neighbor loads
//              (8-load granularity): next half-row's LDGs are in flight
//              while the current half-row reduces -> no latency bubble.
// Warps 12-15: consumers (register-tiled GEMM, packed FFMA2).
// W staged in SMEM (128 KB) + double-buffered 32-row tiles (2 x 32 KB).
// ---------------------------------------------------------------------------
__global__ void __launch_bounds__(THREADS, 1)
sage_layer(const float* __restrict__ nbr,
           const float* __restrict__ selfx,
           const float* __restrict__ W,
           const float* __restrict__ bias,
           float* __restrict__ out,
           int ntiles, int tile0)
{
    extern __shared__ float sm[];
    float* Ws    = sm;                       // [2F][F] = 32768 floats (128 KB)
    float* Abuf0 = sm + TWO_F * F;           // [TILE][2F] (32 KB)
    float* Abuf1 = Abuf0 + TILE * TWO_F;     // second buffer (32 KB)

    const int tid = threadIdx.x;
    const int wid = tid >> 5;
    const int lid = tid & 31;

    // ---- stage W into SMEM (coalesced float4) ----
    {
        float4*       d = (float4*)Ws;
        const float4* s = (const float4*)W;
        #pragma unroll
        for (int t = 0; t < (TWO_F * F / 4) / THREADS; ++t)
            d[tid + t * THREADS] = s[tid + t * THREADS];
    }
    __syncthreads();

    int n = 0;
    for (int t = blockIdx.x; t < ntiles; t += gridDim.x) n++;
    if (n == 0) return;

    const bool producer = (wid < NPROD);
    const float4 bv = ((const float4*)bias)[lid];   // cols 4*lid..4*lid+3

    for (int i = 0; i <= n; ++i) {
        float* bufP = (i & 1) ? Abuf1 : Abuf0;
        float* bufC = (i & 1) ? Abuf0 : Abuf1;

        if (producer) {
            if (i < n) {
                const int  tile = tile0 + blockIdx.x + i * gridDim.x;
                const long tg0  = (long)tile * TILE;

                // self rows -> SMEM via cp.async (latency-immune, zero regs)
                for (int r = wid; r < TILE; r += NPROD)
                    cpa16(bufP + r * TWO_F + F + lid * 4,
                          selfx + (tg0 + r) * F + lid * 4);
                asm volatile("cp.async.commit_group;");

                // neighbor aggregation: rows wid, wid+12 (, wid+24).
                // 3 x 8-load buffers keep ~16 LDG.128 in flight per warp
                // continuously (no per-row latency bubble).
                const int nr = (wid < 8) ? 3 : 2;
                const float4* p0 =
                    (const float4*)(nbr + (tg0 + wid) * (KAGG * F)) + lid;
                const float4* p1 = p0 + (long)12 * (KAGG * F / 4);
                const float4* p2 = p0 + (long)24 * (KAGG * F / 4);

                float4 X[8], Y[8], Z[8];
                LOADH(X, p0, 0);
                LOADH(Y, p0, 1);
                LOADH(Z, p1, 0);
                float4 sa = sum8(X);            // waits X; Y,Z in flight
                LOADH(X, p1, 1);
                float4 sb = sum8(Y);            // waits Y; Z,X in flight
                store_row(bufP, wid, lid, sa, sb);

                if (nr == 3) LOADH(Y, p2, 0);
                sa = sum8(Z);                   // waits Z; X(,Y) in flight
                if (nr == 3) LOADH(Z, p2, 1);
                sb = sum8(X);
                store_row(bufP, wid + 12, lid, sa, sb);

                if (nr == 3) {
                    sa = sum8(Y);
                    sb = sum8(Z);
                    store_row(bufP, wid + 24, lid, sa, sb);
                }
                asm volatile("cp.async.wait_group 0;");
            }
        } else {
            if (i >= 1) {
                const int tile = tile0 + blockIdx.x + (i - 1) * gridDim.x;
                const int cw   = wid - NPROD;              // 0..3
                const float* arow = bufC + (cw * 8) * TWO_F;
                const ulonglong2* Wp = (const ulonglong2*)Ws;

                unsigned long long acc[8][2];
                #pragma unroll
                for (int r = 0; r < 8; ++r) { acc[r][0] = 0ull; acc[r][1] = 0ull; }

                #pragma unroll 2
                for (int f4 = 0; f4 < TWO_F / 4; ++f4) {
                    float4 a[8];
                    #pragma unroll
                    for (int r = 0; r < 8; ++r)            // LDS broadcast (16B)
                        a[r] = ((const float4*)(arow + r * TWO_F))[f4];
                    #pragma unroll
                    for (int j = 0; j < 4; ++j) {
                        const int f = f4 * 4 + j;
                        ulonglong2 wv = Wp[f * (F / 4) + lid];  // LDS.128, conflict-free
                        #pragma unroll
                        for (int r = 0; r < 8; ++r) {
                            float av = (j == 0) ? a[r].x : (j == 1) ? a[r].y
                                     : (j == 2) ? a[r].z : a[r].w;
                            unsigned long long ap = pack2(av);
                            fma2(acc[r][0], wv.x, ap);
                            fma2(acc[r][1], wv.y, ap);
                        }
                    }
                }

                // bias + relu + coalesced store
                #pragma unroll
                for (int r = 0; r < 8; ++r) {
                    float c0, c1, c2, c3;
                    unpack2(acc[r][0], c0, c1);
                    unpack2(acc[r][1], c2, c3);
                    float4 o = make_float4(fmaxf(c0 + bv.x, 0.f),
                                           fmaxf(c1 + bv.y, 0.f),
                                           fmaxf(c2 + bv.z, 0.f),
                                           fmaxf(c3 + bv.w, 0.f));
                    const long rg = (long)tile * TILE + cw * 8 + r;
                    ((float4*)(out + rg * F))[lid] = o;
                }
            }
        }
        __syncthreads();
    }
}

// ---------------------------------------------------------------------------
// Head: z = h0 @ lin1_W + lin1_b ; BatchNorm (batch stats) ; sigmoid(lin2).
// Warp-shuffle reductions (deterministic), 2 barriers total.
// ---------------------------------------------------------------------------
__global__ void __launch_bounds__(256, 1)
head_kernel(const float* __restrict__ h0,
            const float* __restrict__ l1W,   // [F, 8]
            const float* __restrict__ l1b,   // [8]
            const float* __restrict__ gamma, // [8]
            const float* __restrict__ beta,  // [8]
            const float* __restrict__ l2W,   // [8, 2]
            const float* __restrict__ l2b,   // [2]
            float* __restrict__ out)         // [B, 2]
{
    __shared__ float sW[F * 8];
    __shared__ float wsum[8][8];
    __shared__ float wsq [8][8];

    const int i   = threadIdx.x;
    const int wid = i >> 5;
    const int lid = i & 31;

    for (int t = i; t < F * 8; t += 256) sW[t] = l1W[t];
    __syncthreads();

    float z[8];
    #pragma unroll
    for (int j = 0; j < 8; ++j) z[j] = l1b[j];

    const float4* hr = (const float4*)(h0 + (size_t)i * F);
    #pragma unroll
    for (int f4 = 0; f4 < F / 4; ++f4) {
        float4 h = hr[f4];
        #pragma unroll
        for (int j = 0; j < 8; ++j)
            z[j] += h.x * sW[(4 * f4 + 0) * 8 + j]
                  + h.y * sW[(4 * f4 + 1) * 8 + j]
                  + h.z * sW[(4 * f4 + 2) * 8 + j]
                  + h.w * sW[(4 * f4 + 3) * 8 + j];
    }

    // warp-level reduction (deterministic butterfly)
    float rs_[8], rq_[8];
    #pragma unroll
    for (int j = 0; j < 8; ++j) { rs_[j] = z[j]; rq_[j] = z[j] * z[j]; }
    #pragma unroll
    for (int off = 16; off > 0; off >>= 1) {
        #pragma unroll
        for (int j = 0; j < 8; ++j) {
            rs_[j] += __shfl_xor_sync(0xffffffffu, rs_[j], off);
            rq_[j] += __shfl_xor_sync(0xffffffffu, rq_[j], off);
        }
    }
    if (lid == 0) {
        #pragma unroll
        for (int j = 0; j < 8; ++j) { wsum[wid][j] = rs_[j]; wsq[wid][j] = rq_[j]; }
    }
    __syncthreads();

    float zn[8];
    #pragma unroll
    for (int j = 0; j < 8; ++j) {
        float su = 0.f, sq = 0.f;
        #pragma unroll
        for (int w = 0; w < 8; ++w) { su += wsum[w][j]; sq += wsq[w][j]; }
        float mu  = su * (1.0f / 256.0f);
        float var = sq * (1.0f / 256.0f) - mu * mu;
        float rs  = rsqrtf(var + 1e-5f);
        zn[j] = (z[j] - mu) * rs * gamma[j] + beta[j];
    }

    #pragma unroll
    for (int c = 0; c < 2; ++c) {
        float o = l2b[c];
        #pragma unroll
        for (int j = 0; j < 8; ++j) o += zn[j] * l2W[j * 2 + c];
        out[i * 2 + c] = 1.0f / (1.0f + expf(-o));
    }
}

// ---------------------------------------------------------------------------
extern "C" void kernel_launch(void* const* d_in, const int* in_sizes, int n_in,
                              void* d_out, int out_size)
{
    const float* x0    = (const float*)d_in[0];
    const float* x1    = (const float*)d_in[1];
    const float* x2    = (const float*)d_in[2];
    const float* x3    = (const float*)d_in[3];
    const float* W0    = (const float*)d_in[4];
    const float* b0    = (const float*)d_in[5];
    const float* W1    = (const float*)d_in[6];
    const float* b1    = (const float*)d_in[7];
    const float* W2    = (const float*)d_in[8];
    const float* b2    = (const float*)d_in[9];
    const float* l1W   = (const float*)d_in[10];
    const float* l1b   = (const float*)d_in[11];
    const float* gamma = (const float*)d_in[12];
    const float* beta  = (const float*)d_in[13];
    const float* l2W   = (const float*)d_in[14];
    const float* l2b   = (const float*)d_in[15];
    float* out = (float*)d_out;

    void *p2 = nullptr, *p1 = nullptr, *p0 = nullptr;
    cudaGetSymbolAddress(&p2, g_h2);
    cudaGetSymbolAddress(&p1, g_h1);
    cudaGetSymbolAddress(&p0, g_h0);
    float* h2 = (float*)p2;
    float* h1 = (float*)p1;
    float* h0 = (float*)p0;

    const int smem = (TWO_F * F + 2 * TILE * TWO_F) * (int)sizeof(float); // 192 KB
    cudaFuncSetAttribute(sage_layer,
                         cudaFuncAttributeMaxDynamicSharedMemorySize, smem);

    const int grid = 148;
    // Layer i=3 split into two launches (tiles 0-1023, 1024-2047):
    // shifts the ncu -s/-c alignment so the hot kernel gets profiled.
    sage_layer<<<grid, THREADS, smem>>>(x3, x2, W2, b2, h2, 1024, 0);
    sage_layer<<<grid, THREADS, smem>>>(x3, x2, W2, b2, h2, 1024, 1024);
    // Layer i=2: 4096 rows (neighbors: h2, self: x1) -> h1
    sage_layer<<<grid, THREADS, smem>>>(h2, x1, W1, b1, h1, 128, 0);
    // Layer i=1: 256 rows (neighbors: h1, self: x0) -> h0
    sage_layer<<<grid, THREADS, smem>>>(h1, x0, W0, b0, h0, 8, 0);
    // Classifier head
    head_kernel<<<1, 256>>>(h0, l1W, l1b, gamma, beta, l2W, l2b, out);
}

// round 8
// speedup vs baseline: 1.0356x; 1.0356x over previous
#include <cuda_runtime.h>
#include <cuda_bf16.h>
#include <math.h>

#define F        128
#define TWO_F    256
#define KAGG     16
#define TILE     64          // rows per tile
#define THREADS  512
#define B        256

// Scratch (static __device__ arrays: allowed; no runtime allocation)
__device__ float g_h2[65536 * F];   // 33.5 MB
__device__ float g_h1[4096  * F];   // 2 MB
__device__ float g_h0[256   * F];   // 128 KB

// ---- SMEM layout (bytes) --------------------------------------------------
// swizzled bf16 tiles, row stride 512 B (256 k-elems):
//   byte(row,k) = row*512 + (((k>>3) ^ (row&7)) << 4) + (k&7)*2
#define SM_BIAS  0                      // 128 floats (512 B)
#define SM_BHI   1024                   // Wt hi [128n][256k] bf16 (64 KB)
#define SM_BLO   (1024 + 65536)         // Wt lo (64 KB)
#define SM_AHI   (1024 + 131072)        // A hi [64m][256k] bf16 (32 KB)
#define SM_ALO   (1024 + 131072 + 32768) // A lo (32 KB)
#define SM_TOTAL (1024 + 131072 + 65536) // 197632 B

__device__ __forceinline__ unsigned smem_u32(const void* p) {
    unsigned a;
    asm("{ .reg .u64 t; cvta.to.shared.u64 t, %1; cvt.u32.u64 %0, t; }"
        : "=r"(a) : "l"(p));
    return a;
}
__device__ __forceinline__ unsigned pack_bf16x2(float a, float b) {
    unsigned short x = __bfloat16_as_ushort(__float2bfloat16(a));
    unsigned short y = __bfloat16_as_ushort(__float2bfloat16(b));
    return (unsigned)x | ((unsigned)y << 16);
}
__device__ __forceinline__ void ldsm4(unsigned* r, unsigned addr) {
    asm volatile("ldmatrix.sync.aligned.m8n8.x4.shared.b16 {%0,%1,%2,%3}, [%4];"
                 : "=r"(r[0]), "=r"(r[1]), "=r"(r[2]), "=r"(r[3]) : "r"(addr));
}
__device__ __forceinline__ void mma16816(float* c, const unsigned* a,
                                         unsigned b0, unsigned b1) {
    asm volatile(
        "mma.sync.aligned.m16n8k16.row.col.f32.bf16.bf16.f32 "
        "{%0,%1,%2,%3}, {%4,%5,%6,%7}, {%8,%9}, {%0,%1,%2,%3};"
        : "+f"(c[0]), "+f"(c[1]), "+f"(c[2]), "+f"(c[3])
        : "r"(a[0]), "r"(a[1]), "r"(a[2]), "r"(a[3]), "r"(b0), "r"(b1));
}

// ---------------------------------------------------------------------------
// Tensor-core fused SAGE layer (baseline-PTX HMMA, bf16 hi/lo 3-product split)
//   out[r] = relu( concat(mean_16 nbr[r], self[r]) @ W + b )
// Persistent CTAs, 512 thr. Phase 1: all warps aggregate -> swizzled bf16
// hi/lo A tile. Phase 2: 16 warps GEMM m16xn32 each via ldmatrix + mma.sync.
// ---------------------------------------------------------------------------
__global__ void __launch_bounds__(THREADS, 1)
sage_mma(const float* __restrict__ nbr,
         const float* __restrict__ selfx,
         const float* __restrict__ W,
         const float* __restrict__ bias,
         float* __restrict__ out,
         int ntiles)
{
    extern __shared__ char sm[];
    const int tid = threadIdx.x;
    const int wid = tid >> 5;
    const int lid = tid & 31;
    const unsigned smb = smem_u32(sm);

    // ---- stage W^T hi/lo (swizzled) + bias, once per CTA ----
    for (int idx = tid; idx < TWO_F * F; idx += THREADS) {
        const int k = idx >> 7, n = idx & 127;
        const float w = W[idx];
        const float whf = __bfloat162float(__float2bfloat16(w));
        const unsigned off = (unsigned)n * 512
                           + ((((unsigned)k >> 3) ^ ((unsigned)n & 7)) << 4)
                           + ((unsigned)k & 7) * 2;
        *(unsigned short*)(sm + SM_BHI + off) =
            __bfloat16_as_ushort(__float2bfloat16(w));
        *(unsigned short*)(sm + SM_BLO + off) =
            __bfloat16_as_ushort(__float2bfloat16(w - whf));
    }
    if (tid < F) ((float*)(sm + SM_BIAS))[tid] = bias[tid];
    __syncthreads();

    const float* bias_s = (const float*)(sm + SM_BIAS);
    const unsigned m0 = (unsigned)(wid >> 2) * 16;   // warp's M-block
    const unsigned n0 = (unsigned)(wid & 3) * 32;    // warp's N-block

    // ldmatrix lane geometry (shared by A and B)
    const unsigned row_off = (lid & 7) + ((lid >> 3) & 1) * 8;
    const unsigned chalf   = (unsigned)(lid >> 4);   // k8-half select

    for (int t = blockIdx.x; t < ntiles; t += gridDim.x) {
        const long tg0 = (long)t * TILE;

        // ---- phase 1: aggregate + self -> swizzled bf16 hi/lo A tile ----
        // warp handles rows wid*4 .. wid*4+3; lane = feature (float4 = 4 k)
        {
            const unsigned l2 = (unsigned)(lid >> 1);      // 16B chunk within 128 k
            const unsigned sub8 = (unsigned)(lid & 1) * 8; // 8B half of chunk
            #pragma unroll
            for (int rr = 0; rr < 4; ++rr) {
                const int row = wid * 4 + rr;
                const long rg = tg0 + row;
                const unsigned rbase = (unsigned)row * 512;
                const unsigned rx = (unsigned)row & 7;

                // mean over 16 neighbors
                const float4* nb = (const float4*)(nbr + rg * (KAGG * F)) + lid;
                float4 v[KAGG];
                #pragma unroll
                for (int k = 0; k < KAGG; ++k) v[k] = nb[k * (F / 4)];
                #pragma unroll
                for (int s = KAGG / 2; s > 0; s >>= 1)
                    #pragma unroll
                    for (int k = 0; k < s; ++k) {
                        v[k].x += v[k + s].x; v[k].y += v[k + s].y;
                        v[k].z += v[k + s].z; v[k].w += v[k + s].w;
                    }
                const float sc = 1.0f / 16.0f;
                float a0 = v[0].x * sc, a1 = v[0].y * sc;
                float a2 = v[0].z * sc, a3 = v[0].w * sc;

                // agg half: k = 4*lid (chunk l2, half sub8)
                unsigned offA = rbase + ((l2 ^ rx) << 4) + sub8;
                {
                    float h0 = __bfloat162float(__float2bfloat16(a0));
                    float h1 = __bfloat162float(__float2bfloat16(a1));
                    float h2 = __bfloat162float(__float2bfloat16(a2));
                    float h3 = __bfloat162float(__float2bfloat16(a3));
                    *(uint2*)(sm + SM_AHI + offA) =
                        make_uint2(pack_bf16x2(a0, a1), pack_bf16x2(a2, a3));
                    *(uint2*)(sm + SM_ALO + offA) =
                        make_uint2(pack_bf16x2(a0 - h0, a1 - h1),
                                   pack_bf16x2(a2 - h2, a3 - h3));
                }
                // self half: k = 128 + 4*lid (chunk 16+l2)
                float4 sv = ((const float4*)(selfx + rg * F))[lid];
                unsigned offS = rbase + (((16u + l2) ^ rx) << 4) + sub8;
                {
                    float h0 = __bfloat162float(__float2bfloat16(sv.x));
                    float h1 = __bfloat162float(__float2bfloat16(sv.y));
                    float h2 = __bfloat162float(__float2bfloat16(sv.z));
                    float h3 = __bfloat162float(__float2bfloat16(sv.w));
                    *(uint2*)(sm + SM_AHI + offS) =
                        make_uint2(pack_bf16x2(sv.x, sv.y), pack_bf16x2(sv.z, sv.w));
                    *(uint2*)(sm + SM_ALO + offS) =
                        make_uint2(pack_bf16x2(sv.x - h0, sv.y - h1),
                                   pack_bf16x2(sv.z - h2, sv.w - h3));
                }
            }
        }
        __syncthreads();

        // ---- phase 2: GEMM. warp computes rows [m0,m0+16) x cols [n0,n0+32) ----
        {
            float c[4][4];
            #pragma unroll
            for (int j = 0; j < 4; ++j)
                #pragma unroll
                for (int q = 0; q < 4; ++q) c[j][q] = 0.f;

            const unsigned rA  = m0 + row_off;
            const unsigned rAb = rA * 512, rAx = rA & 7;
            const unsigned rB0  = n0 + row_off;          // n-block pair 0
            const unsigned rB0b = rB0 * 512, rB0x = rB0 & 7;
            const unsigned rB1  = n0 + 16 + row_off;     // n-block pair 1
            const unsigned rB1b = rB1 * 512, rB1x = rB1 & 7;

            #pragma unroll
            for (int s = 0; s < 16; ++s) {
                const unsigned ch = (unsigned)(s * 2) + chalf;
                unsigned ahi[4], alo[4], bh0[4], bh1[4], bl0[4], bl1[4];
                ldsm4(ahi, smb + SM_AHI + rAb  + ((ch ^ rAx)  << 4));
                ldsm4(alo, smb + SM_ALO + rAb  + ((ch ^ rAx)  << 4));
                ldsm4(bh0, smb + SM_BHI + rB0b + ((ch ^ rB0x) << 4));
                ldsm4(bh1, smb + SM_BHI + rB1b + ((ch ^ rB1x) << 4));
                ldsm4(bl0, smb + SM_BLO + rB0b + ((ch ^ rB0x) << 4));
                ldsm4(bl1, smb + SM_BLO + rB1b + ((ch ^ rB1x) << 4));

                // n-blocks: j=0 -> {bh0[0],bh0[2]}, j=1 -> {bh0[1],bh0[3]},
                //           j=2 -> {bh1[0],bh1[2]}, j=3 -> {bh1[1],bh1[3]}
                mma16816(c[0], ahi, bh0[0], bh0[2]);
                mma16816(c[1], ahi, bh0[1], bh0[3]);
                mma16816(c[2], ahi, bh1[0], bh1[2]);
                mma16816(c[3], ahi, bh1[1], bh1[3]);
                mma16816(c[0], ahi, bl0[0], bl0[2]);
                mma16816(c[1], ahi, bl0[1], bl0[3]);
                mma16816(c[2], ahi, bl1[0], bl1[2]);
                mma16816(c[3], ahi, bl1[1], bl1[3]);
                mma16816(c[0], alo, bh0[0], bh0[2]);
                mma16816(c[1], alo, bh0[1], bh0[3]);
                mma16816(c[2], alo, bh1[0], bh1[2]);
                mma16816(c[3], alo, bh1[1], bh1[3]);
            }

            // ---- epilogue: bias + relu + store ----
            const int g = lid >> 2, tt = lid & 3;
            const long row1 = tg0 + m0 + g;
            const long row2 = row1 + 8;
            #pragma unroll
            for (int j = 0; j < 4; ++j) {
                const int col = n0 + j * 8 + tt * 2;
                const float b0 = bias_s[col], b1 = bias_s[col + 1];
                float2 o1 = make_float2(fmaxf(c[j][0] + b0, 0.f),
                                        fmaxf(c[j][1] + b1, 0.f));
                float2 o2 = make_float2(fmaxf(c[j][2] + b0, 0.f),
                                        fmaxf(c[j][3] + b1, 0.f));
                *(float2*)(out + row1 * F + col) = o1;
                *(float2*)(out + row2 * F + col) = o2;
            }
        }
        __syncthreads();
    }
}

// ---------------------------------------------------------------------------
// Head: z = h0 @ lin1_W + lin1_b ; BatchNorm (batch stats) ; sigmoid(lin2).
// ---------------------------------------------------------------------------
__global__ void __launch_bounds__(256, 1)
head_kernel(const float* __restrict__ h0,
            const float* __restrict__ l1W,   // [F, 8]
            const float* __restrict__ l1b,   // [8]
            const float* __restrict__ gamma, // [8]
            const float* __restrict__ beta,  // [8]
            const float* __restrict__ l2W,   // [8, 2]
            const float* __restrict__ l2b,   // [2]
            float* __restrict__ out)         // [B, 2]
{
    __shared__ float sW[F * 8];
    __shared__ float wsum[8][8];
    __shared__ float wsq [8][8];

    const int i   = threadIdx.x;
    const int wid = i >> 5;
    const int lid = i & 31;

    for (int t = i; t < F * 8; t += 256) sW[t] = l1W[t];
    __syncthreads();

    float z[8];
    #pragma unroll
    for (int j = 0; j < 8; ++j) z[j] = l1b[j];

    const float4* hr = (const float4*)(h0 + (size_t)i * F);
    #pragma unroll
    for (int f4 = 0; f4 < F / 4; ++f4) {
        float4 h = hr[f4];
        #pragma unroll
        for (int j = 0; j < 8; ++j)
            z[j] += h.x * sW[(4 * f4 + 0) * 8 + j]
                  + h.y * sW[(4 * f4 + 1) * 8 + j]
                  + h.z * sW[(4 * f4 + 2) * 8 + j]
                  + h.w * sW[(4 * f4 + 3) * 8 + j];
    }

    float rs_[8], rq_[8];
    #pragma unroll
    for (int j = 0; j < 8; ++j) { rs_[j] = z[j]; rq_[j] = z[j] * z[j]; }
    #pragma unroll
    for (int off = 16; off > 0; off >>= 1) {
        #pragma unroll
        for (int j = 0; j < 8; ++j) {
            rs_[j] += __shfl_xor_sync(0xffffffffu, rs_[j], off);
            rq_[j] += __shfl_xor_sync(0xffffffffu, rq_[j], off);
        }
    }
    if (lid == 0) {
        #pragma unroll
        for (int j = 0; j < 8; ++j) { wsum[wid][j] = rs_[j]; wsq[wid][j] = rq_[j]; }
    }
    __syncthreads();

    float zn[8];
    #pragma unroll
    for (int j = 0; j < 8; ++j) {
        float su = 0.f, sq = 0.f;
        #pragma unroll
        for (int w = 0; w < 8; ++w) { su += wsum[w][j]; sq += wsq[w][j]; }
        float mu  = su * (1.0f / 256.0f);
        float var = sq * (1.0f / 256.0f) - mu * mu;
        float rs  = rsqrtf(var + 1e-5f);
        zn[j] = (z[j] - mu) * rs * gamma[j] + beta[j];
    }

    #pragma unroll
    for (int c = 0; c < 2; ++c) {
        float o = l2b[c];
        #pragma unroll
        for (int j = 0; j < 8; ++j) o += zn[j] * l2W[j * 2 + c];
        out[i * 2 + c] = 1.0f / (1.0f + expf(-o));
    }
}

// ---------------------------------------------------------------------------
extern "C" void kernel_launch(void* const* d_in, const int* in_sizes, int n_in,
                              void* d_out, int out_size)
{
    const float* x0    = (const float*)d_in[0];
    const float* x1    = (const float*)d_in[1];
    const float* x2    = (const float*)d_in[2];
    const float* x3    = (const float*)d_in[3];
    const float* W0    = (const float*)d_in[4];
    const float* b0    = (const float*)d_in[5];
    const float* W1    = (const float*)d_in[6];
    const float* b1    = (const float*)d_in[7];
    const float* W2    = (const float*)d_in[8];
    const float* b2    = (const float*)d_in[9];
    const float* l1W   = (const float*)d_in[10];
    const float* l1b   = (const float*)d_in[11];
    const float* gamma = (const float*)d_in[12];
    const float* beta  = (const float*)d_in[13];
    const float* l2W   = (const float*)d_in[14];
    const float* l2b   = (const float*)d_in[15];
    float* out = (float*)d_out;

    void *p2 = nullptr, *p1 = nullptr, *p0 = nullptr;
    cudaGetSymbolAddress(&p2, g_h2);
    cudaGetSymbolAddress(&p1, g_h1);
    cudaGetSymbolAddress(&p0, g_h0);
    float* h2 = (float*)p2;
    float* h1 = (float*)p1;
    float* h0 = (float*)p0;

    cudaFuncSetAttribute(sage_mma,
                         cudaFuncAttributeMaxDynamicSharedMemorySize, SM_TOTAL);

    // Layer i=3: 65536 rows -> 1024 tiles of 64
    sage_mma<<<148, THREADS, SM_TOTAL>>>(x3, x2, W2, b2, h2, 1024);
    // Layer i=2: 4096 rows -> 64 tiles
    sage_mma<<<64, THREADS, SM_TOTAL>>>(h2, x1, W1, b1, h1, 64);
    // Layer i=1: 256 rows -> 4 tiles
    sage_mma<<<4, THREADS, SM_TOTAL>>>(h1, x0, W0, b0, h0, 4);
    // Classifier head
    head_kernel<<<1, 256>>>(h0, l1W, l1b, gamma, beta, l2W, l2b, out);
}

// round 9
// speedup vs baseline: 1.0910x; 1.0536x over previous
#include <cuda_runtime.h>
#include <cuda_bf16.h>
#include <math.h>

#define F        128
#define TWO_F    256
#define KAGG     16
#define TILE     32          // rows per tile
#define NPROD    12          // producer warps
#define THREADS  512
#define B        256

// Scratch (static __device__ arrays: allowed; no runtime allocation)
__device__ float g_h2[65536 * F];   // 33.5 MB
__device__ float g_h1[4096  * F];   // 2 MB
__device__ float g_h0[256   * F];   // 128 KB

// ---- SMEM layout (bytes) --------------------------------------------------
// swizzled bf16 tiles, row stride 512 B (256 k-elems):
//   byte(row,k) = row*512 + (((k>>3) ^ (row&7)) << 4) + (k&7)*2
#define SM_BIAS  0                        // 128 floats
#define SM_BHI   1024                     // Wt hi [128n][256k] bf16 (64 KB)
#define SM_BLO   (SM_BHI + 65536)         // Wt lo (64 KB)
#define SM_A     (SM_BLO + 65536)         // 2 buffers x (hi 16 KB + lo 16 KB)
#define ABUF_SZ  (TILE * 512)             // 16384 B per half
#define SM_TOTAL (SM_A + 4 * ABUF_SZ)     // 197632 B

__device__ __forceinline__ unsigned smem_u32(const void* p) {
    unsigned a;
    asm("{ .reg .u64 t; cvta.to.shared.u64 t, %1; cvt.u32.u64 %0, t; }"
        : "=r"(a) : "l"(p));
    return a;
}
__device__ __forceinline__ unsigned pack_bf16x2(float a, float b) {
    unsigned short x = __bfloat16_as_ushort(__float2bfloat16(a));
    unsigned short y = __bfloat16_as_ushort(__float2bfloat16(b));
    return (unsigned)x | ((unsigned)y << 16);
}
__device__ __forceinline__ void ldsm4(unsigned* r, unsigned addr) {
    asm volatile("ldmatrix.sync.aligned.m8n8.x4.shared.b16 {%0,%1,%2,%3}, [%4];"
                 : "=r"(r[0]), "=r"(r[1]), "=r"(r[2]), "=r"(r[3]) : "r"(addr));
}
__device__ __forceinline__ void mma16816(float* c, const unsigned* a,
                                         unsigned b0, unsigned b1) {
    asm volatile(
        "mma.sync.aligned.m16n8k16.row.col.f32.bf16.bf16.f32 "
        "{%0,%1,%2,%3}, {%4,%5,%6,%7}, {%8,%9}, {%0,%1,%2,%3};"
        : "+f"(c[0]), "+f"(c[1]), "+f"(c[2]), "+f"(c[3])
        : "r"(a[0]), "r"(a[1]), "r"(a[2]), "r"(a[3]), "r"(b0), "r"(b1));
}

// ---------------------------------------------------------------------------
// Warp-specialized tensor-core SAGE layer.
//   out[r] = relu( concat(mean_16 nbr[r], self[r]) @ W + b )
// Persistent CTAs, 512 thr = 16 warps, 1 CTA/SM (193 KB smem).
// Warps 0-11 : producers — aggregate + bf16 hi/lo split into double-buffered
//              swizzled A tiles. Memory streams CONTINUOUSLY (no idle phase).
// Warps 12-15: consumers — HMMA GEMM (bf16 hi/lo, 3-product split), each warp
//              m16 x n64 of the 32x128 output tile. ~2.3k cyc << producer
//              ~9k cyc DRAM share, so iteration time == memory time.
// ---------------------------------------------------------------------------
__global__ void __launch_bounds__(THREADS, 1)
sage_mma(const float* __restrict__ nbr,
         const float* __restrict__ selfx,
         const float* __restrict__ W,
         const float* __restrict__ bias,
         float* __restrict__ out,
         int ntiles)
{
    extern __shared__ char sm[];
    const int tid = threadIdx.x;
    const int wid = tid >> 5;
    const int lid = tid & 31;
    const unsigned smb = smem_u32(sm);

    int n = 0;
    for (int t = blockIdx.x; t < ntiles; t += gridDim.x) n++;
    if (n == 0) return;

    // ---- stage W^T hi/lo (swizzled) + bias, once per CTA ----
    for (int idx = tid; idx < TWO_F * F; idx += THREADS) {
        const int k = idx >> 7, nn = idx & 127;
        const float w = W[idx];
        const float whf = __bfloat162float(__float2bfloat16(w));
        const unsigned off = (unsigned)nn * 512
                           + ((((unsigned)k >> 3) ^ ((unsigned)nn & 7)) << 4)
                           + ((unsigned)k & 7) * 2;
        *(unsigned short*)(sm + SM_BHI + off) =
            __bfloat16_as_ushort(__float2bfloat16(w));
        *(unsigned short*)(sm + SM_BLO + off) =
            __bfloat16_as_ushort(__float2bfloat16(w - whf));
    }
    if (tid < F) ((float*)(sm + SM_BIAS))[tid] = bias[tid];
    __syncthreads();

    const float* bias_s = (const float*)(sm + SM_BIAS);
    const bool producer = (wid < NPROD);

    // ldmatrix lane geometry
    const unsigned row_off = (lid & 7) + ((lid >> 3) & 1) * 8;
    const unsigned chalf   = (unsigned)(lid >> 4);

    for (int i = 0; i <= n; ++i) {
        const unsigned pb = (i & 1) ? (SM_A + 2 * ABUF_SZ) : SM_A;     // fill
        const unsigned cb = (i & 1) ? SM_A : (SM_A + 2 * ABUF_SZ);     // drain

        if (producer) {
            if (i < n) {
                const int  tile = blockIdx.x + i * gridDim.x;
                const long tg0  = (long)tile * TILE;
                const unsigned l2 = (unsigned)(lid >> 1);
                const unsigned sub8 = (unsigned)(lid & 1) * 8;

                for (int row = wid; row < TILE; row += NPROD) {
                    const long rg = tg0 + row;
                    const unsigned rbase = (unsigned)row * 512;
                    const unsigned rx = (unsigned)row & 7;

                    // mean over 16 neighbors (lane = feature, float4 = 4 k)
                    const float4* nb =
                        (const float4*)(nbr + rg * (KAGG * F)) + lid;
                    float4 v[KAGG];
                    #pragma unroll
                    for (int k = 0; k < KAGG; ++k) v[k] = nb[k * (F / 4)];
                    #pragma unroll
                    for (int s = KAGG / 2; s > 0; s >>= 1)
                        #pragma unroll
                        for (int k = 0; k < s; ++k) {
                            v[k].x += v[k + s].x; v[k].y += v[k + s].y;
                            v[k].z += v[k + s].z; v[k].w += v[k + s].w;
                        }
                    const float sc = 1.0f / 16.0f;
                    float a0 = v[0].x * sc, a1 = v[0].y * sc;
                    float a2 = v[0].z * sc, a3 = v[0].w * sc;

                    // agg half: k = 4*lid
                    unsigned offA = rbase + ((l2 ^ rx) << 4) + sub8;
                    {
                        float h0 = __bfloat162float(__float2bfloat16(a0));
                        float h1 = __bfloat162float(__float2bfloat16(a1));
                        float h2 = __bfloat162float(__float2bfloat16(a2));
                        float h3 = __bfloat162float(__float2bfloat16(a3));
                        *(uint2*)(sm + pb + offA) =
                            make_uint2(pack_bf16x2(a0, a1), pack_bf16x2(a2, a3));
                        *(uint2*)(sm + pb + ABUF_SZ + offA) =
                            make_uint2(pack_bf16x2(a0 - h0, a1 - h1),
                                       pack_bf16x2(a2 - h2, a3 - h3));
                    }
                    // self half: k = 128 + 4*lid
                    float4 sv = ((const float4*)(selfx + rg * F))[lid];
                    unsigned offS = rbase + (((16u + l2) ^ rx) << 4) + sub8;
                    {
                        float h0 = __bfloat162float(__float2bfloat16(sv.x));
                        float h1 = __bfloat162float(__float2bfloat16(sv.y));
                        float h2 = __bfloat162float(__float2bfloat16(sv.z));
                        float h3 = __bfloat162float(__float2bfloat16(sv.w));
                        *(uint2*)(sm + pb + offS) =
                            make_uint2(pack_bf16x2(sv.x, sv.y),
                                       pack_bf16x2(sv.z, sv.w));
                        *(uint2*)(sm + pb + ABUF_SZ + offS) =
                            make_uint2(pack_bf16x2(sv.x - h0, sv.y - h1),
                                       pack_bf16x2(sv.z - h2, sv.w - h3));
                    }
                }
            }
        } else if (i >= 1) {
            const int  tile = blockIdx.x + (i - 1) * gridDim.x;
            const long tg0  = (long)tile * TILE;
            const int  cw   = wid - NPROD;            // 0..3
            const unsigned m0 = (unsigned)(cw >> 1) * 16;
            const unsigned n0 = (unsigned)(cw & 1) * 64;

            float c[8][4];
            #pragma unroll
            for (int j = 0; j < 8; ++j)
                #pragma unroll
                for (int q = 0; q < 4; ++q) c[j][q] = 0.f;

            const unsigned rA  = m0 + row_off;
            const unsigned rAb = rA * 512, rAx = rA & 7;
            unsigned rBb[4], rBx[4];
            #pragma unroll
            for (int j = 0; j < 4; ++j) {
                const unsigned rB = n0 + j * 16 + row_off;
                rBb[j] = rB * 512; rBx[j] = rB & 7;
            }

            #pragma unroll
            for (int s = 0; s < 16; ++s) {
                const unsigned ch = (unsigned)(s * 2) + chalf;
                unsigned ahi[4], alo[4];
                ldsm4(ahi, smb + cb + rAb + ((ch ^ rAx) << 4));
                ldsm4(alo, smb + cb + ABUF_SZ + rAb + ((ch ^ rAx) << 4));
                #pragma unroll
                for (int j = 0; j < 4; ++j) {
                    unsigned bh[4], bl[4];
                    ldsm4(bh, smb + SM_BHI + rBb[j] + ((ch ^ rBx[j]) << 4));
                    ldsm4(bl, smb + SM_BLO + rBb[j] + ((ch ^ rBx[j]) << 4));
                    mma16816(c[2*j],   ahi, bh[0], bh[2]);
                    mma16816(c[2*j+1], ahi, bh[1], bh[3]);
                    mma16816(c[2*j],   ahi, bl[0], bl[2]);
                    mma16816(c[2*j+1], ahi, bl[1], bl[3]);
                    mma16816(c[2*j],   alo, bh[0], bh[2]);
                    mma16816(c[2*j+1], alo, bh[1], bh[3]);
                }
            }

            // epilogue: bias + relu + store (m16 x n64)
            const int g = lid >> 2, tt = lid & 3;
            const long row1 = tg0 + m0 + g;
            const long row2 = row1 + 8;
            #pragma unroll
            for (int j = 0; j < 8; ++j) {
                const int col = n0 + j * 8 + tt * 2;
                const float b0 = bias_s[col], b1 = bias_s[col + 1];
                float2 o1 = make_float2(fmaxf(c[j][0] + b0, 0.f),
                                        fmaxf(c[j][1] + b1, 0.f));
                float2 o2 = make_float2(fmaxf(c[j][2] + b0, 0.f),
                                        fmaxf(c[j][3] + b1, 0.f));
                *(float2*)(out + row1 * F + col) = o1;
                *(float2*)(out + row2 * F + col) = o2;
            }
        }
        __syncthreads();
    }
}

// ---------------------------------------------------------------------------
// Head: z = h0 @ lin1_W + lin1_b ; BatchNorm (batch stats) ; sigmoid(lin2).
// ---------------------------------------------------------------------------
__global__ void __launch_bounds__(256, 1)
head_kernel(const float* __restrict__ h0,
            const float* __restrict__ l1W,   // [F, 8]
            const float* __restrict__ l1b,   // [8]
            const float* __restrict__ gamma, // [8]
            const float* __restrict__ beta,  // [8]
            const float* __restrict__ l2W,   // [8, 2]
            const float* __restrict__ l2b,   // [2]
            float* __restrict__ out)         // [B, 2]
{
    __shared__ float sW[F * 8];
    __shared__ float wsum[8][8];
    __shared__ float wsq [8][8];

    const int i   = threadIdx.x;
    const int wid = i >> 5;
    const int lid = i & 31;

    for (int t = i; t < F * 8; t += 256) sW[t] = l1W[t];
    __syncthreads();

    float z[8];
    #pragma unroll
    for (int j = 0; j < 8; ++j) z[j] = l1b[j];

    const float4* hr = (const float4*)(h0 + (size_t)i * F);
    #pragma unroll
    for (int f4 = 0; f4 < F / 4; ++f4) {
        float4 h = hr[f4];
        #pragma unroll
        for (int j = 0; j < 8; ++j)
            z[j] += h.x * sW[(4 * f4 + 0) * 8 + j]
                  + h.y * sW[(4 * f4 + 1) * 8 + j]
                  + h.z * sW[(4 * f4 + 2) * 8 + j]
                  + h.w * sW[(4 * f4 + 3) * 8 + j];
    }

    float rs_[8], rq_[8];
    #pragma unroll
    for (int j = 0; j < 8; ++j) { rs_[j] = z[j]; rq_[j] = z[j] * z[j]; }
    #pragma unroll
    for (int off = 16; off > 0; off >>= 1) {
        #pragma unroll
        for (int j = 0; j < 8; ++j) {
            rs_[j] += __shfl_xor_sync(0xffffffffu, rs_[j], off);
            rq_[j] += __shfl_xor_sync(0xffffffffu, rq_[j], off);
        }
    }
    if (lid == 0) {
        #pragma unroll
        for (int j = 0; j < 8; ++j) { wsum[wid][j] = rs_[j]; wsq[wid][j] = rq_[j]; }
    }
    __syncthreads();

    float zn[8];
    #pragma unroll
    for (int j = 0; j < 8; ++j) {
        float su = 0.f, sq = 0.f;
        #pragma unroll
        for (int w = 0; w < 8; ++w) { su += wsum[w][j]; sq += wsq[w][j]; }
        float mu  = su * (1.0f / 256.0f);
        float var = sq * (1.0f / 256.0f) - mu * mu;
        float rs  = rsqrtf(var + 1e-5f);
        zn[j] = (z[j] - mu) * rs * gamma[j] + beta[j];
    }

    #pragma unroll
    for (int c = 0; c < 2; ++c) {
        float o = l2b[c];
        #pragma unroll
        for (int j = 0; j < 8; ++j) o += zn[j] * l2W[j * 2 + c];
        out[i * 2 + c] = 1.0f / (1.0f + expf(-o));
    }
}

// ---------------------------------------------------------------------------
extern "C" void kernel_launch(void* const* d_in, const int* in_sizes, int n_in,
                              void* d_out, int out_size)
{
    const float* x0    = (const float*)d_in[0];
    const float* x1    = (const float*)d_in[1];
    const float* x2    = (const float*)d_in[2];
    const float* x3    = (const float*)d_in[3];
    const float* W0    = (const float*)d_in[4];
    const float* b0    = (const float*)d_in[5];
    const float* W1    = (const float*)d_in[6];
    const float* b1    = (const float*)d_in[7];
    const float* W2    = (const float*)d_in[8];
    const float* b2    = (const float*)d_in[9];
    const float* l1W   = (const float*)d_in[10];
    const float* l1b   = (const float*)d_in[11];
    const float* gamma = (const float*)d_in[12];
    const float* beta  = (const float*)d_in[13];
    const float* l2W   = (const float*)d_in[14];
    const float* l2b   = (const float*)d_in[15];
    float* out = (float*)d_out;

    void *p2 = nullptr, *p1 = nullptr, *p0 = nullptr;
    cudaGetSymbolAddress(&p2, g_h2);
    cudaGetSymbolAddress(&p1, g_h1);
    cudaGetSymbolAddress(&p0, g_h0);
    float* h2 = (float*)p2;
    float* h1 = (float*)p1;
    float* h0 = (float*)p0;

    cudaFuncSetAttribute(sage_mma,
                         cudaFuncAttributeMaxDynamicSharedMemorySize, SM_TOTAL);

    // Layer i=3: 65536 rows -> 2048 tiles of 32
    sage_mma<<<148, THREADS, SM_TOTAL>>>(x3, x2, W2, b2, h2, 2048);
    // Layer i=2: 4096 rows -> 128 tiles
    sage_mma<<<128, THREADS, SM_TOTAL>>>(h2, x1, W1, b1, h1, 128);
    // Layer i=1: 256 rows -> 8 tiles
    sage_mma<<<8, THREADS, SM_TOTAL>>>(h1, x0, W0, b0, h0, 8);
    // Classifier head
    head_kernel<<<1, 256>>>(h0, l1W, l1b, gamma, beta, l2W, l2b, out);
}

// round 11
// speedup vs baseline: 1.2136x; 1.1124x over previous
#include <cuda_runtime.h>
#include <cuda_bf16.h>
#include <math.h>

#define F        128
#define TWO_F    256
#define KAGG     16
#define TILE     32          // rows per tile
#define NPROD    12          // producer warps
#define THREADS  512
#define B        256

// Scratch (static __device__ arrays: allowed; no runtime allocation)
__device__ float g_h2m[4096 * F];   // 16-row means of h2 (2 MB)
__device__ float g_h1m[256  * F];   // 16-row means of h1 (128 KB)
__device__ float g_h0 [256  * F];   // h0 (128 KB)

// ---- SMEM layout (bytes) --------------------------------------------------
// swizzled bf16 tiles, row stride 512 B (256 k-elems):
//   byte(row,k) = row*512 + (((k>>3) ^ (row&7)) << 4) + (k&7)*2
#define SM_BIAS  0                        // 128 floats
#define SM_BHI   1024                     // Wt hi [128n][256k] bf16 (64 KB)
#define SM_BLO   (SM_BHI + 65536)         // Wt lo (64 KB)
#define SM_A     (SM_BLO + 65536)         // 2 buffers x (hi 16 KB + lo 16 KB)
#define ABUF_SZ  (TILE * 512)             // 16384 B per half
#define SM_TOTAL (SM_A + 4 * ABUF_SZ)     // 197632 B

__device__ __forceinline__ unsigned smem_u32(const void* p) {
    unsigned a;
    asm("{ .reg .u64 t; cvta.to.shared.u64 t, %1; cvt.u32.u64 %0, t; }"
        : "=r"(a) : "l"(p));
    return a;
}
__device__ __forceinline__ unsigned pack_bf16x2(float a, float b) {
    unsigned short x = __bfloat16_as_ushort(__float2bfloat16(a));
    unsigned short y = __bfloat16_as_ushort(__float2bfloat16(b));
    return (unsigned)x | ((unsigned)y << 16);
}
__device__ __forceinline__ void ldsm4(unsigned* r, unsigned addr) {
    asm volatile("ldmatrix.sync.aligned.m8n8.x4.shared.b16 {%0,%1,%2,%3}, [%4];"
                 : "=r"(r[0]), "=r"(r[1]), "=r"(r[2]), "=r"(r[3]) : "r"(addr));
}
__device__ __forceinline__ void mma16816(float* c, const unsigned* a,
                                         unsigned b0, unsigned b1) {
    asm volatile(
        "mma.sync.aligned.m16n8k16.row.col.f32.bf16.bf16.f32 "
        "{%0,%1,%2,%3}, {%4,%5,%6,%7}, {%8,%9}, {%0,%1,%2,%3};"
        : "+f"(c[0]), "+f"(c[1]), "+f"(c[2]), "+f"(c[3])
        : "r"(a[0]), "r"(a[1]), "r"(a[2]), "r"(a[3]), "r"(b0), "r"(b1));
}

// store one row's concat halves (bf16 hi/lo split) into swizzled A buffer
__device__ __forceinline__ void store_half(char* sm, unsigned pb, unsigned rbase,
                                           unsigned rx, unsigned l2, unsigned sub8,
                                           unsigned kchunk_base,
                                           float a0, float a1, float a2, float a3) {
    const unsigned off = rbase + (((kchunk_base + l2) ^ rx) << 4) + sub8;
    float h0 = __bfloat162float(__float2bfloat16(a0));
    float h1 = __bfloat162float(__float2bfloat16(a1));
    float h2 = __bfloat162float(__float2bfloat16(a2));
    float h3 = __bfloat162float(__float2bfloat16(a3));
    *(uint2*)(sm + pb + off) =
        make_uint2(pack_bf16x2(a0, a1), pack_bf16x2(a2, a3));
    *(uint2*)(sm + pb + ABUF_SZ + off) =
        make_uint2(pack_bf16x2(a0 - h0, a1 - h1), pack_bf16x2(a2 - h2, a3 - h3));
}

// ---------------------------------------------------------------------------
// Warp-specialized tensor-core SAGE layer.
// AGG_IN=1 : concat(mean_16 nbr[r*16..], self[r]);  AGG_IN=0: concat(nbr[r], self[r])
// MEAN_OUT=1: write only 16-row group means of relu output (out has ntiles*2 rows)
// MEAN_OUT=0: write full relu output rows.
// ---------------------------------------------------------------------------
template<int AGG_IN, int MEAN_OUT>
__global__ void __launch_bounds__(THREADS, 1)
sage_mma(const float* __restrict__ nbr,
         const float* __restrict__ selfx,
         const float* __restrict__ W,
         const float* __restrict__ bias,
         float* __restrict__ out,
         int ntiles)
{
    extern __shared__ char sm[];
    const int tid = threadIdx.x;
    const int wid = tid >> 5;
    const int lid = tid & 31;
    const unsigned smb = smem_u32(sm);

    int n = 0;
    for (int t = blockIdx.x; t < ntiles; t += gridDim.x) n++;
    if (n == 0) return;

    // ---- stage W^T hi/lo: one 16B chunk (8 k-values, 1 n) per thread-iter.
    // STS.128, conflict-free. Reads are stride-512B scalar (L2$-friendly).
    for (int c = tid; c < 32 * F; c += THREADS) {
        const int nn = c >> 5, ch = c & 31;
        float w[8], wh[8];
        #pragma unroll
        for (int i = 0; i < 8; ++i) {
            w[i]  = W[(ch * 8 + i) * F + nn];
            wh[i] = __bfloat162float(__float2bfloat16(w[i]));
        }
        uint4 hi, lo;
        hi.x = pack_bf16x2(w[0], w[1]); hi.y = pack_bf16x2(w[2], w[3]);
        hi.z = pack_bf16x2(w[4], w[5]); hi.w = pack_bf16x2(w[6], w[7]);
        lo.x = pack_bf16x2(w[0]-wh[0], w[1]-wh[1]);
        lo.y = pack_bf16x2(w[2]-wh[2], w[3]-wh[3]);
        lo.z = pack_bf16x2(w[4]-wh[4], w[5]-wh[5]);
        lo.w = pack_bf16x2(w[6]-wh[6], w[7]-wh[7]);
        const unsigned off = (unsigned)nn * 512
                           + (((unsigned)(ch ^ (nn & 7))) << 4);
        *(uint4*)(sm + SM_BHI + off) = hi;
        *(uint4*)(sm + SM_BLO + off) = lo;
    }
    if (tid < F) ((float*)(sm + SM_BIAS))[tid] = bias[tid];
    __syncthreads();

    const float* bias_s = (const float*)(sm + SM_BIAS);
    const bool producer = (wid < NPROD);

    // ldmatrix lane geometry
    const unsigned row_off = (lid & 7) + ((lid >> 3) & 1) * 8;
    const unsigned chalf   = (unsigned)(lid >> 4);

    for (int i = 0; i <= n; ++i) {
        const unsigned pb = (i & 1) ? (SM_A + 2 * ABUF_SZ) : SM_A;     // fill
        const unsigned cb = (i & 1) ? SM_A : (SM_A + 2 * ABUF_SZ);     // drain

        if (producer) {
            if (i < n) {
                const int  tile = blockIdx.x + i * gridDim.x;
                const long tg0  = (long)tile * TILE;
                const unsigned l2 = (unsigned)(lid >> 1);
                const unsigned sub8 = (unsigned)(lid & 1) * 8;

                for (int row = wid; row < TILE; row += NPROD) {
                    const long rg = tg0 + row;
                    const unsigned rbase = (unsigned)row * 512;
                    const unsigned rx = (unsigned)row & 7;

                    float a0, a1, a2, a3;
                    if (AGG_IN) {
                        // mean over 16 neighbors (lane = feature, float4 = 4 k)
                        const float4* nb =
                            (const float4*)(nbr + rg * (KAGG * F)) + lid;
                        float4 v[KAGG];
                        #pragma unroll
                        for (int k = 0; k < KAGG; ++k) v[k] = nb[k * (F / 4)];
                        #pragma unroll
                        for (int s = KAGG / 2; s > 0; s >>= 1)
                            #pragma unroll
                            for (int k = 0; k < s; ++k) {
                                v[k].x += v[k + s].x; v[k].y += v[k + s].y;
                                v[k].z += v[k + s].z; v[k].w += v[k + s].w;
                            }
                        const float sc = 1.0f / 16.0f;
                        a0 = v[0].x * sc; a1 = v[0].y * sc;
                        a2 = v[0].z * sc; a3 = v[0].w * sc;
                    } else {
                        float4 p = ((const float4*)(nbr + rg * F))[lid];
                        a0 = p.x; a1 = p.y; a2 = p.z; a3 = p.w;
                    }
                    store_half(sm, pb, rbase, rx, l2, sub8, 0u, a0, a1, a2, a3);
                    float4 sv = ((const float4*)(selfx + rg * F))[lid];
                    store_half(sm, pb, rbase, rx, l2, sub8, 16u,
                               sv.x, sv.y, sv.z, sv.w);
                }
            }
        } else if (i >= 1) {
            const int  tile = blockIdx.x + (i - 1) * gridDim.x;
            const long tg0  = (long)tile * TILE;
            const int  cw   = wid - NPROD;            // 0..3
            const unsigned m0 = (unsigned)(cw >> 1) * 16;
            const unsigned n0 = (unsigned)(cw & 1) * 64;

            float c[8][4];
            #pragma unroll
            for (int j = 0; j < 8; ++j)
                #pragma unroll
                for (int q = 0; q < 4; ++q) c[j][q] = 0.f;

            const unsigned rA  = m0 + row_off;
            const unsigned rAb = rA * 512, rAx = rA & 7;
            unsigned rBb[4], rBx[4];
            #pragma unroll
            for (int j = 0; j < 4; ++j) {
                const unsigned rB = n0 + j * 16 + row_off;
                rBb[j] = rB * 512; rBx[j] = rB & 7;
            }

            #pragma unroll
            for (int s = 0; s < 16; ++s) {
                const unsigned ch = (unsigned)(s * 2) + chalf;
                unsigned ahi[4], alo[4];
                ldsm4(ahi, smb + cb + rAb + ((ch ^ rAx) << 4));
                ldsm4(alo, smb + cb + ABUF_SZ + rAb + ((ch ^ rAx) << 4));
                #pragma unroll
                for (int j = 0; j < 4; ++j) {
                    unsigned bh[4], bl[4];
                    ldsm4(bh, smb + SM_BHI + rBb[j] + ((ch ^ rBx[j]) << 4));
                    ldsm4(bl, smb + SM_BLO + rBb[j] + ((ch ^ rBx[j]) << 4));
                    mma16816(c[2*j],   ahi, bh[0], bh[2]);
                    mma16816(c[2*j+1], ahi, bh[1], bh[3]);
                    mma16816(c[2*j],   ahi, bl[0], bl[2]);
                    mma16816(c[2*j+1], ahi, bl[1], bl[3]);
                    mma16816(c[2*j],   alo, bh[0], bh[2]);
                    mma16816(c[2*j+1], alo, bh[1], bh[3]);
                }
            }

            // ---- epilogue ----
            const int g = lid >> 2, tt = lid & 3;
            if (MEAN_OUT) {
                // relu, then sum this warp's 16 rows per column, write means
                float sj[8][2];
                #pragma unroll
                for (int j = 0; j < 8; ++j) {
                    const int col = n0 + j * 8 + tt * 2;
                    const float b0 = bias_s[col], b1 = bias_s[col + 1];
                    sj[j][0] = fmaxf(c[j][0] + b0, 0.f) + fmaxf(c[j][2] + b0, 0.f);
                    sj[j][1] = fmaxf(c[j][1] + b1, 0.f) + fmaxf(c[j][3] + b1, 0.f);
                }
                #pragma unroll
                for (int off = 4; off <= 16; off <<= 1)
                    #pragma unroll
                    for (int j = 0; j < 8; ++j) {
                        sj[j][0] += __shfl_xor_sync(0xffffffffu, sj[j][0], off);
                        sj[j][1] += __shfl_xor_sync(0xffffffffu, sj[j][1], off);
                    }
                if (lid < 4) {
                    const long grow = (long)tile * 2 + (m0 >> 4);
                    #pragma unroll
                    for (int j = 0; j < 8; ++j)
                        *(float2*)(out + grow * F + n0 + j * 8 + lid * 2) =
                            make_float2(sj[j][0] * (1.0f / 16.0f),
                                        sj[j][1] * (1.0f / 16.0f));
                }
            } else {
                const long row1 = tg0 + m0 + g;
                const long row2 = row1 + 8;
                #pragma unroll
                for (int j = 0; j < 8; ++j) {
                    const int col = n0 + j * 8 + tt * 2;
                    const float b0 = bias_s[col], b1 = bias_s[col + 1];
                    float2 o1 = make_float2(fmaxf(c[j][0] + b0, 0.f),
                                            fmaxf(c[j][1] + b1, 0.f));
                    float2 o2 = make_float2(fmaxf(c[j][2] + b0, 0.f),
                                            fmaxf(c[j][3] + b1, 0.f));
                    *(float2*)(out + row1 * F + col) = o1;
                    *(float2*)(out + row2 * F + col) = o2;
                }
            }
        }
        __syncthreads();
    }
}

// ---------------------------------------------------------------------------
// Head: z = h0 @ lin1_W + lin1_b ; BatchNorm (batch stats) ; sigmoid(lin2).
// h0 staged coalesced into swizzled SMEM (conflict-free row reads).
// ---------------------------------------------------------------------------
#define HS_H0   0
#define HS_W    (B * F)            // floats
#define HS_SUM  (HS_W + F * 8)
#define HS_SQ   (HS_SUM + 64)
#define HS_TOTAL ((HS_SQ + 64) * 4)

__global__ void __launch_bounds__(256, 1)
head_kernel(const float* __restrict__ h0,
            const float* __restrict__ l1W,   // [F, 8]
            const float* __restrict__ l1b,   // [8]
            const float* __restrict__ gamma, // [8]
            const float* __restrict__ beta,  // [8]
            const float* __restrict__ l2W,   // [8, 2]
            const float* __restrict__ l2b,   // [2]
            float* __restrict__ out)         // [B, 2]
{
    extern __shared__ float hsm[];
    float* sh0  = hsm + HS_H0;
    float* sW   = hsm + HS_W;
    float* wsum = hsm + HS_SUM;
    float* wsq  = hsm + HS_SQ;

    const int i   = threadIdx.x;
    const int wid = i >> 5;
    const int lid = i & 31;

    // coalesced stage of h0 with per-row XOR swizzle (conflict-free reads)
    {
        const float4* g4 = (const float4*)h0;
        float4* s4 = (float4*)sh0;
        #pragma unroll
        for (int it = 0; it < (B * F / 4) / 256; ++it) {
            const int idx = i + it * 256;
            const int row = idx >> 5, q = idx & 31;
            s4[row * 32 + (q ^ (row & 31))] = g4[idx];
        }
    }
    for (int t = i; t < F * 8; t += 256) sW[t] = l1W[t];
    __syncthreads();

    float z[8];
    #pragma unroll
    for (int j = 0; j < 8; ++j) z[j] = l1b[j];

    const float4* hr = (const float4*)sh0 + (size_t)i * 32;
    #pragma unroll
    for (int f4 = 0; f4 < F / 4; ++f4) {
        float4 h = hr[f4 ^ (i & 31)];
        #pragma unroll
        for (int j = 0; j < 8; ++j)
            z[j] += h.x * sW[(4 * f4 + 0) * 8 + j]
                  + h.y * sW[(4 * f4 + 1) * 8 + j]
                  + h.z * sW[(4 * f4 + 2) * 8 + j]
                  + h.w * sW[(4 * f4 + 3) * 8 + j];
    }

    float rs_[8], rq_[8];
    #pragma unroll
    for (int j = 0; j < 8; ++j) { rs_[j] = z[j]; rq_[j] = z[j] * z[j]; }
    #pragma unroll
    for (int off = 16; off > 0; off >>= 1) {
        #pragma unroll
        for (int j = 0; j < 8; ++j) {
            rs_[j] += __shfl_xor_sync(0xffffffffu, rs_[j], off);
            rq_[j] += __shfl_xor_sync(0xffffffffu, rq_[j], off);
        }
    }
    if (lid == 0) {
        #pragma unroll
        for (int j = 0; j < 8; ++j) {
            wsum[wid * 8 + j] = rs_[j];
            wsq [wid * 8 + j] = rq_[j];
        }
    }
    __syncthreads();

    float zn[8];
    #pragma unroll
    for (int j = 0; j < 8; ++j) {
        float su = 0.f, sq = 0.f;
        #pragma unroll
        for (int w = 0; w < 8; ++w) { su += wsum[w * 8 + j]; sq += wsq[w * 8 + j]; }
        float mu  = su * (1.0f / 256.0f);
        float var = sq * (1.0f / 256.0f) - mu * mu;
        float rs  = rsqrtf(var + 1e-5f);
        zn[j] = (z[j] - mu) * rs * gamma[j] + beta[j];
    }

    #pragma unroll
    for (int c = 0; c < 2; ++c) {
        float o = l2b[c];
        #pragma unroll
        for (int j = 0; j < 8; ++j) o += zn[j] * l2W[j * 2 + c];
        out[i * 2 + c] = 1.0f / (1.0f + expf(-o));
    }
}

// ---------------------------------------------------------------------------
extern "C" void kernel_launch(void* const* d_in, const int* in_sizes, int n_in,
                              void* d_out, int out_size)
{
    const float* x0    = (const float*)d_in[0];
    const float* x1    = (const float*)d_in[1];
    const float* x2    = (const float*)d_in[2];
    const float* x3    = (const float*)d_in[3];
    const float* W0    = (const float*)d_in[4];
    const float* b0    = (const float*)d_in[5];
    const float* W1    = (const float*)d_in[6];
    const float* b1    = (const float*)d_in[7];
    const float* W2    = (const float*)d_in[8];
    const float* b2    = (const float*)d_in[9];
    const float* l1W   = (const float*)d_in[10];
    const float* l1b   = (const float*)d_in[11];
    const float* gamma = (const float*)d_in[12];
    const float* beta  = (const float*)d_in[13];
    const float* l2W   = (const float*)d_in[14];
    const float* l2b   = (const float*)d_in[15];
    float* out = (float*)d_out;

    void *p2 = nullptr, *p1 = nullptr, *p0 = nullptr;
    cudaGetSymbolAddress(&p2, g_h2m);
    cudaGetSymbolAddress(&p1, g_h1m);
    cudaGetSymbolAddress(&p0, g_h0);
    float* h2m = (float*)p2;
    float* h1m = (float*)p1;
    float* h0  = (float*)p0;

    cudaFuncSetAttribute(sage_mma<1, 1>,
                         cudaFuncAttributeMaxDynamicSharedMemorySize, SM_TOTAL);
    cudaFuncSetAttribute(sage_mma<0, 1>,
                         cudaFuncAttributeMaxDynamicSharedMemorySize, SM_TOTAL);
    cudaFuncSetAttribute(sage_mma<0, 0>,
                         cudaFuncAttributeMaxDynamicSharedMemorySize, SM_TOTAL);
    cudaFuncSetAttribute(head_kernel,
                         cudaFuncAttributeMaxDynamicSharedMemorySize, HS_TOTAL);

    // K3: agg(x3) ++ x2 -> relu GEMM -> 16-row means only (h2m: 4096 x 128)
    sage_mma<1, 1><<<148, THREADS, SM_TOTAL>>>(x3, x2, W2, b2, h2m, 2048);
    // K2: h2m ++ x1 -> relu GEMM -> 16-row means only (h1m: 256 x 128)
    sage_mma<0, 1><<<128, THREADS, SM_TOTAL>>>(h2m, x1, W1, b1, h1m, 128);
    // K1: h1m ++ x0 -> relu GEMM -> full h0 (256 x 128)
    sage_mma<0, 0><<<8, THREADS, SM_TOTAL>>>(h1m, x0, W0, b0, h0, 8);
    // Head
    head_kernel<<<1, 256, HS_TOTAL>>>(h0, l1W, l1b, gamma, beta, l2W, l2b, out);
}